// round 4
// baseline (speedup 1.0000x reference)
#include <cuda_runtime.h>
#include <cstdint>

// out[m,n] = relu( sum_k x[m,k] * W[n,k] + b[n] )
// M=131072, N=256, K=256 fp32.
// mma.sync m16n8k8 tf32. BM=256 BN=128 BK=32, triple-buffered cp.async,
// W pre-rounded to tf32 once (removes B-side cvt from mainloop).

#define BM 256
#define BN 128
#define BK 32
#define LDA 36                                  // padded float stride, conflict-free
#define KDIM 256
#define NDIM 256
#define STAGE_FLOATS ((BM + BN) * LDA)          // 13824 floats per stage
#define SMEM_BYTES (3 * STAGE_FLOATS * 4)       // 165888 B, triple buffer

__device__ float g_Wr[NDIM * KDIM];             // tf32-rounded W (256 KB static)

__device__ __forceinline__ uint32_t f2tf32(float f) {
    uint32_t r;
    asm("cvt.rna.tf32.f32 %0, %1;" : "=r"(r) : "f"(f));
    return r;
}

__global__ void round_W_kernel(const float* __restrict__ W) {
    int i = blockIdx.x * 1024 + threadIdx.x;    // 64 blocks x 1024 = 65536
    g_Wr[i] = __uint_as_float(f2tf32(W[i]));
}

__global__ void __launch_bounds__(512, 1)
gemm_tf32_relu2(const float* __restrict__ X, const float* __restrict__ bias,
                float* __restrict__ Out)
{
    extern __shared__ float smem[];

    const int tid  = threadIdx.x;
    const int lane = tid & 31;
    const int warp = tid >> 5;          // 0..15
    const int warpM = warp & 7;         // 8 x 32-row M slices
    const int warpN = warp >> 3;        // 2 x 64-col N slices

    const int ctaM = blockIdx.x * BM;
    const int ctaN = blockIdx.y * BN;

    const int r = lane >> 2;            // 0..7
    const int c = lane & 3;             // 0..3

    float acc[2][8][4];
#pragma unroll
    for (int i = 0; i < 2; i++)
#pragma unroll
        for (int j = 0; j < 8; j++)
#pragma unroll
            for (int q = 0; q < 4; q++) acc[i][j][q] = 0.0f;

    // ---- stage loader: chunk kk -> stage st (0,1,2) ----
    auto fill = [&](int kk, int st) {
        float* As = smem + st * STAGE_FLOATS;
        float* Bs = As + BM * LDA;
        const float* gA = X + (size_t)ctaM * KDIM + kk * BK;
#pragma unroll
        for (int i = 0; i < 4; i++) {                    // 256 rows x 8 x 16B
            int s = tid + i * 512;
            int row = s >> 3, c16 = s & 7;
            uint32_t d = (uint32_t)__cvta_generic_to_shared(&As[row * LDA + c16 * 4]);
            asm volatile("cp.async.cg.shared.global [%0], [%1], 16;"
                         :: "r"(d), "l"(gA + (size_t)row * KDIM + c16 * 4));
        }
        const float* gB = g_Wr + (size_t)ctaN * KDIM + kk * BK;
#pragma unroll
        for (int i = 0; i < 2; i++) {                    // 128 rows x 8 x 16B
            int s = tid + i * 512;
            int row = s >> 3, c16 = s & 7;
            uint32_t d = (uint32_t)__cvta_generic_to_shared(&Bs[row * LDA + c16 * 4]);
            asm volatile("cp.async.cg.shared.global [%0], [%1], 16;"
                         :: "r"(d), "l"(gB + (size_t)row * KDIM + c16 * 4));
        }
    };

    auto compute = [&](int st) {
        const float* A0 = smem + st * STAGE_FLOATS + (warpM * 32) * LDA;
        const float* B0 = smem + st * STAGE_FLOATS + BM * LDA + (warpN * 64) * LDA;
#pragma unroll
        for (int ks = 0; ks < 4; ks++) {
            const int kb = ks * 8;
            uint32_t a[2][4];
#pragma unroll
            for (int mt = 0; mt < 2; mt++) {
                const float* ap = A0 + (mt * 16 + r) * LDA + kb + c;
                a[mt][0] = f2tf32(ap[0]);
                a[mt][1] = f2tf32(ap[8 * LDA]);
                a[mt][2] = f2tf32(ap[4]);
                a[mt][3] = f2tf32(ap[8 * LDA + 4]);
            }
#pragma unroll
            for (int nt = 0; nt < 8; nt++) {
                const float* bp = B0 + (nt * 8 + r) * LDA + kb + c;
                uint32_t b0 = __float_as_uint(bp[0]);    // pre-rounded: no cvt
                uint32_t b1 = __float_as_uint(bp[4]);
#pragma unroll
                for (int mt = 0; mt < 2; mt++) {
                    asm volatile(
                        "mma.sync.aligned.m16n8k8.row.col.f32.tf32.tf32.f32 "
                        "{%0,%1,%2,%3}, {%4,%5,%6,%7}, {%8,%9}, {%0,%1,%2,%3};\n"
                        : "+f"(acc[mt][nt][0]), "+f"(acc[mt][nt][1]),
                          "+f"(acc[mt][nt][2]), "+f"(acc[mt][nt][3])
                        : "r"(a[mt][0]), "r"(a[mt][1]), "r"(a[mt][2]), "r"(a[mt][3]),
                          "r"(b0), "r"(b1));
                }
            }
        }
    };

    // ---- mainloop: 8 K-chunks, triple buffer, one sync per chunk ----
    fill(0, 0);
    asm volatile("cp.async.commit_group;" ::: "memory");
    fill(1, 1);
    asm volatile("cp.async.commit_group;" ::: "memory");

#pragma unroll 1
    for (int kk = 0; kk < KDIM / BK; ++kk) {
        if (kk < 7) asm volatile("cp.async.wait_group 1;" ::: "memory");
        else        asm volatile("cp.async.wait_group 0;" ::: "memory");
        __syncthreads();   // chunk kk ready; all warps done reading stage (kk-1)%3
        if (kk + 2 < KDIM / BK) {
            fill(kk + 2, (kk + 2) % 3);   // overwrites stage (kk-1)%3 — safe
            asm volatile("cp.async.commit_group;" ::: "memory");
        }
        compute(kk % 3);
    }

    // ---- epilogue: bias + relu, float2 stores ----
#pragma unroll
    for (int mt = 0; mt < 2; mt++) {
        const int m0 = ctaM + warpM * 32 + mt * 16 + r;
#pragma unroll
        for (int nt = 0; nt < 8; nt++) {
            const int n0 = ctaN + warpN * 64 + nt * 8 + 2 * c;
            const float bv0 = __ldg(&bias[n0]);
            const float bv1 = __ldg(&bias[n0 + 1]);
            float v0 = fmaxf(acc[mt][nt][0] + bv0, 0.0f);
            float v1 = fmaxf(acc[mt][nt][1] + bv1, 0.0f);
            float v2 = fmaxf(acc[mt][nt][2] + bv0, 0.0f);
            float v3 = fmaxf(acc[mt][nt][3] + bv1, 0.0f);
            *(float2*)&Out[(size_t)m0 * NDIM + n0]       = make_float2(v0, v1);
            *(float2*)&Out[(size_t)(m0 + 8) * NDIM + n0] = make_float2(v2, v3);
        }
    }
}

extern "C" void kernel_launch(void* const* d_in, const int* in_sizes, int n_in,
                              void* d_out, int out_size)
{
    const float* x = (const float*)d_in[0];   // [131072, 256]
    const float* W = (const float*)d_in[1];   // [256, 256]
    const float* b = (const float*)d_in[2];   // [256]
    float* out = (float*)d_out;

    round_W_kernel<<<64, 1024>>>(W);

    cudaFuncSetAttribute(gemm_tf32_relu2,
                         cudaFuncAttributeMaxDynamicSharedMemorySize, SMEM_BYTES);
    dim3 grid(131072 / BM, NDIM / BN);        // (512, 2) = 1024 CTAs
    gemm_tf32_relu2<<<grid, 512, SMEM_BYTES>>>(x, b, out);
}

// round 5
// speedup vs baseline: 1.7626x; 1.7626x over previous
#include <cuda_runtime.h>
#include <cuda_fp16.h>
#include <cstdint>

// out[m,n] = relu( sum_k x[m,k] * W[n,k] + b[n] )
// M=131072, N=256, K=256 fp32 in/out.
// fp16 mma.sync m16n8k16 (same 10-bit mantissa as tf32, 2x rate).
// BM=128, BN=256 (full N), BK=64 halves = 128B SW128 rows, double buffer.
// A: fp32 LDG -> cvt -> STS (reg-prefetched 1 chunk ahead). W: fp16 prepass.

#define BM   128
#define NDIM 256
#define KDIM 256
#define BKH  64                      // K per chunk (halves)
#define NCH  (KDIM / BKH)            // 4 chunks

#define ABUF (BM * 128)              // 16 KB per stage (128B/row)
#define BBUF (NDIM * 128)            // 32 KB per stage
#define SMEM_BYTES (2 * ABUF + 2 * BBUF)   // 96 KB

__device__ __half g_Wh[NDIM * KDIM];       // 128 KB fp16 W

__global__ void convW_kernel(const float* __restrict__ W) {
    int i = blockIdx.x * 1024 + threadIdx.x;   // 64 x 1024 = 65536
    g_Wh[i] = __float2half_rn(W[i]);
}

__device__ __forceinline__ uint32_t pack_h2(float lo, float hi) {
    uint32_t d;
    asm("cvt.rn.f16x2.f32 %0, %1, %2;" : "=r"(d) : "f"(hi), "f"(lo));  // d={hi,lo}
    return d;
}

__global__ void __launch_bounds__(512, 1)
gemm_f16_relu(const float* __restrict__ X, const float* __restrict__ bias,
              float* __restrict__ Out)
{
    extern __shared__ char smem[];
    const uint32_t sbase = (uint32_t)__cvta_generic_to_shared(smem);
    // stages: A0 | A1 | B0 | B1
    const uint32_t sA[2] = { sbase,            sbase + ABUF };
    const uint32_t sB[2] = { sbase + 2*ABUF,   sbase + 2*ABUF + BBUF };

    const int tid  = threadIdx.x;
    const int lane = tid & 31;
    const int warp = tid >> 5;          // 0..15
    const int warpM = warp & 3;         // 4 x 32-row slices of BM=128
    const int warpN = warp >> 2;        // 4 x 64-col slices of N=256
    const int ctaM = blockIdx.x * BM;

    const int xr  = lane >> 2;          // 0..7 : fragment row-in-group, also swizzle key
    const int c4b = (lane & 3) * 4;     // byte offset of k-pair within 16B unit

    float acc[2][8][4];
#pragma unroll
    for (int i = 0; i < 2; i++)
#pragma unroll
        for (int j = 0; j < 8; j++)
#pragma unroll
            for (int q = 0; q < 4; q++) acc[i][j][q] = 0.0f;

    // ---- A global prefetch (fp32) : 128 rows x 64 floats / 512 thr = 4 float4 ----
    float4 pf[4];
    auto ldgA = [&](int ch) {
#pragma unroll
        for (int i = 0; i < 4; i++) {
            int f = tid + i * 512;                 // 0..2047
            int row = f >> 4, q = f & 15;          // 16 float4 per row
            pf[i] = __ldg((const float4*)(X + (size_t)(ctaM + row) * KDIM + ch * BKH + q * 4));
        }
    };
    // ---- A convert + store to swizzled fp16 smem ----
    auto stsA = [&](int buf) {
#pragma unroll
        for (int i = 0; i < 4; i++) {
            int f = tid + i * 512;
            int row = f >> 4, q = f & 15;          // q = 8B slot index (4 halves)
            uint32_t h01 = pack_h2(pf[i].x, pf[i].y);
            uint32_t h23 = pack_h2(pf[i].z, pf[i].w);
            uint32_t addr = sA[buf] + row * 128
                          + ((((q >> 1) ^ (row & 7)) << 4) | ((q & 1) << 3));
            asm volatile("st.shared.v2.b32 [%0], {%1, %2};"
                         :: "r"(addr), "r"(h01), "r"(h23) : "memory");
        }
    };
    // ---- B (fp16 W) cp.async : 256 rows x 8 x 16B / 512 thr = 4 granules ----
    auto cpB = [&](int ch, int buf) {
#pragma unroll
        for (int i = 0; i < 4; i++) {
            int s = tid + i * 512;                 // 0..2047
            int row = s >> 3, u16 = s & 7;
            uint32_t dst = sB[buf] + row * 128 + ((u16 ^ (row & 7)) << 4);
            const __half* src = g_Wh + (size_t)row * KDIM + ch * BKH + u16 * 8;
            asm volatile("cp.async.cg.shared.global [%0], [%1], 16;"
                         :: "r"(dst), "l"(src));
        }
    };

    // ---- prologue ----
    ldgA(0);
    cpB(0, 0);
    asm volatile("cp.async.commit_group;" ::: "memory");

#pragma unroll 1
    for (int ch = 0; ch < NCH; ++ch) {
        const int buf = ch & 1;
        stsA(buf);                                   // A chunk ch (prev use: ch-2, safe)
        asm volatile("cp.async.wait_group 0;" ::: "memory");
        __syncthreads();                             // A + B chunk ch visible to all
        if (ch + 1 < NCH) {
            ldgA(ch + 1);                            // hidden under compute
            cpB(ch + 1, buf ^ 1);
            asm volatile("cp.async.commit_group;" ::: "memory");
        }

        // ---- compute chunk: 4 k16-steps ----
        const uint32_t aBase = sA[buf] + (warpM * 32 + xr) * 128 + c4b;
        const uint32_t bBase = sB[buf] + (warpN * 64 + xr) * 128 + c4b;
#pragma unroll
        for (int ks = 0; ks < 4; ks++) {
            const uint32_t o0 = (uint32_t)(((2 * ks)     ^ xr) << 4);
            const uint32_t o1 = (uint32_t)(((2 * ks + 1) ^ xr) << 4);
            uint32_t a[2][4];
#pragma unroll
            for (int mt = 0; mt < 2; mt++) {
                const uint32_t ab = aBase + mt * 2048;     // +16 rows
                asm volatile("ld.shared.b32 %0, [%1];" : "=r"(a[mt][0]) : "r"(ab + o0));
                asm volatile("ld.shared.b32 %0, [%1];" : "=r"(a[mt][1]) : "r"(ab + 1024 + o0));
                asm volatile("ld.shared.b32 %0, [%1];" : "=r"(a[mt][2]) : "r"(ab + o1));
                asm volatile("ld.shared.b32 %0, [%1];" : "=r"(a[mt][3]) : "r"(ab + 1024 + o1));
            }
#pragma unroll
            for (int nt = 0; nt < 8; nt++) {
                const uint32_t bb = bBase + nt * 1024;     // +8 n-rows
                uint32_t b0, b1;
                asm volatile("ld.shared.b32 %0, [%1];" : "=r"(b0) : "r"(bb + o0));
                asm volatile("ld.shared.b32 %0, [%1];" : "=r"(b1) : "r"(bb + o1));
#pragma unroll
                for (int mt = 0; mt < 2; mt++) {
                    asm volatile(
                        "mma.sync.aligned.m16n8k16.row.col.f32.f16.f16.f32 "
                        "{%0,%1,%2,%3}, {%4,%5,%6,%7}, {%8,%9}, {%0,%1,%2,%3};\n"
                        : "+f"(acc[mt][nt][0]), "+f"(acc[mt][nt][1]),
                          "+f"(acc[mt][nt][2]), "+f"(acc[mt][nt][3])
                        : "r"(a[mt][0]), "r"(a[mt][1]), "r"(a[mt][2]), "r"(a[mt][3]),
                          "r"(b0), "r"(b1));
                }
            }
        }
    }

    // ---- epilogue: bias + relu, float2 stores ----
#pragma unroll
    for (int mt = 0; mt < 2; mt++) {
        const int m0 = ctaM + warpM * 32 + mt * 16 + xr;
#pragma unroll
        for (int nt = 0; nt < 8; nt++) {
            const int n0 = warpN * 64 + nt * 8 + 2 * (lane & 3);
            const float bv0 = __ldg(&bias[n0]);
            const float bv1 = __ldg(&bias[n0 + 1]);
            float v0 = fmaxf(acc[mt][nt][0] + bv0, 0.0f);
            float v1 = fmaxf(acc[mt][nt][1] + bv1, 0.0f);
            float v2 = fmaxf(acc[mt][nt][2] + bv0, 0.0f);
            float v3 = fmaxf(acc[mt][nt][3] + bv1, 0.0f);
            *(float2*)&Out[(size_t)m0 * NDIM + n0]       = make_float2(v0, v1);
            *(float2*)&Out[(size_t)(m0 + 8) * NDIM + n0] = make_float2(v2, v3);
        }
    }
}

extern "C" void kernel_launch(void* const* d_in, const int* in_sizes, int n_in,
                              void* d_out, int out_size)
{
    const float* x = (const float*)d_in[0];   // [131072, 256]
    const float* W = (const float*)d_in[1];   // [256, 256]
    const float* b = (const float*)d_in[2];   // [256]
    float* out = (float*)d_out;

    convW_kernel<<<64, 1024>>>(W);

    cudaFuncSetAttribute(gemm_f16_relu,
                         cudaFuncAttributeMaxDynamicSharedMemorySize, SMEM_BYTES);
    dim3 grid(131072 / BM);                   // 1024 CTAs, full N per CTA
    gemm_f16_relu<<<grid, 512, SMEM_BYTES>>>(x, b, out);
}

// round 6
// speedup vs baseline: 1.8087x; 1.0262x over previous
#include <cuda_runtime.h>
#include <cuda_fp16.h>
#include <cstdint>

// out[m,n] = relu( sum_k x[m,k] * W[n,k] + b[n] )
// M=131072, N=256, K=256 fp32 in/out.
// fp16 mma.sync m16n8k16 + ldmatrix fragment feed.
// BM=128, BN=256 (full N), BK=64 halves, XOR-swizzled 128B rows, double buffer.

#define BM   128
#define NDIM 256
#define KDIM 256
#define BKH  64                      // K per chunk (halves)
#define NCH  (KDIM / BKH)            // 4 chunks

#define ABUF (BM * 128)              // 16 KB per stage
#define BBUF (NDIM * 128)            // 32 KB per stage
#define SMEM_BYTES (2 * ABUF + 2 * BBUF)   // 96 KB

__device__ __half g_Wh[NDIM * KDIM];       // 128 KB fp16 W

__global__ void convW_kernel(const float* __restrict__ W) {
    int i = blockIdx.x * 1024 + threadIdx.x;   // 64 x 1024 = 65536
    g_Wh[i] = __float2half_rn(W[i]);
}

__device__ __forceinline__ uint32_t pack_h2(float lo, float hi) {
    uint32_t d;
    asm("cvt.rn.f16x2.f32 %0, %1, %2;" : "=r"(d) : "f"(hi), "f"(lo));
    return d;
}

__device__ __forceinline__ void ldsm_x4(uint32_t* r, uint32_t addr) {
    asm volatile("ldmatrix.sync.aligned.m8n8.x4.shared.b16 {%0,%1,%2,%3}, [%4];"
                 : "=r"(r[0]), "=r"(r[1]), "=r"(r[2]), "=r"(r[3]) : "r"(addr));
}

__global__ void __launch_bounds__(512, 1)
gemm_f16_ldsm(const float* __restrict__ X, const float* __restrict__ bias,
              float* __restrict__ Out)
{
    extern __shared__ char smem[];
    const uint32_t sbase = (uint32_t)__cvta_generic_to_shared(smem);
    const uint32_t sA[2] = { sbase,          sbase + ABUF };
    const uint32_t sB[2] = { sbase + 2*ABUF, sbase + 2*ABUF + BBUF };

    const int tid  = threadIdx.x;
    const int lane = tid & 31;
    const int warp = tid >> 5;          // 0..15
    const int warpM = warp & 3;         // 4 x 32-row M slices
    const int warpN = warp >> 2;        // 4 x 64-col N slices
    const int ctaM = blockIdx.x * BM;

    // ldmatrix lane decomposition: j = row within 8x8 matrix, mat = which matrix
    const int j   = lane & 7;
    const int mat = lane >> 3;

    // A x4: mat0=rows0-7/kg0, mat1=rows8-15/kg0, mat2=rows0-7/kg1, mat3=rows8-15/kg1
    // -> regs r0..r3 = a0..a3 of m16n8k16
    uint32_t aOff[2];
#pragma unroll
    for (int mt = 0; mt < 2; mt++) {
        const int arow = warpM * 32 + mt * 16 + (mat & 1) * 8 + j;
        const int akg  = mat >> 1;
        aOff[mt] = (uint32_t)(arow * 128 + ((akg ^ j) << 4));
    }
    // B x4 per n16-pair p: mat0=n0-7/kg0, mat1=n0-7/kg1, mat2=n8-15/kg0, mat3=n8-15/kg1
    // -> r0,r1 = b0,b1 (nt=2p) ; r2,r3 = b0,b1 (nt=2p+1)
    uint32_t bOff[4];
#pragma unroll
    for (int p = 0; p < 4; p++) {
        const int brow = warpN * 64 + p * 16 + (mat >> 1) * 8 + j;
        const int bkg  = mat & 1;
        bOff[p] = (uint32_t)(brow * 128 + ((bkg ^ j) << 4));
    }

    float acc[2][8][4];
#pragma unroll
    for (int i = 0; i < 2; i++)
#pragma unroll
        for (int jj = 0; jj < 8; jj++)
#pragma unroll
            for (int q = 0; q < 4; q++) acc[i][jj][q] = 0.0f;

    // ---- A global prefetch (fp32): 128 rows x 16 f4 slots = 2048 / 512 thr ----
    float4 pf[4];
    auto ldgA = [&](int ch) {
#pragma unroll
        for (int i = 0; i < 4; i++) {
            int f = tid + i * 512;
            int row = f >> 4, q = f & 15;
            pf[i] = __ldg((const float4*)(X + (size_t)(ctaM + row) * KDIM + ch * BKH + q * 4));
        }
    };
    auto stsA = [&](int buf) {
#pragma unroll
        for (int i = 0; i < 4; i++) {
            int f = tid + i * 512;
            int row = f >> 4, q = f & 15;          // q = 8B slot
            uint32_t h01 = pack_h2(pf[i].x, pf[i].y);
            uint32_t h23 = pack_h2(pf[i].z, pf[i].w);
            uint32_t addr = sA[buf] + row * 128
                          + ((((q >> 1) ^ (row & 7)) << 4) | ((q & 1) << 3));
            asm volatile("st.shared.v2.b32 [%0], {%1, %2};"
                         :: "r"(addr), "r"(h01), "r"(h23) : "memory");
        }
    };
    auto cpB = [&](int ch, int buf) {
#pragma unroll
        for (int i = 0; i < 4; i++) {
            int s = tid + i * 512;
            int row = s >> 3, u16 = s & 7;
            uint32_t dst = sB[buf] + row * 128 + ((u16 ^ (row & 7)) << 4);
            const __half* src = g_Wh + (size_t)row * KDIM + ch * BKH + u16 * 8;
            asm volatile("cp.async.cg.shared.global [%0], [%1], 16;"
                         :: "r"(dst), "l"(src));
        }
    };

    // ---- prologue ----
    ldgA(0);
    cpB(0, 0);
    asm volatile("cp.async.commit_group;" ::: "memory");

#pragma unroll 1
    for (int ch = 0; ch < NCH; ++ch) {
        const int buf = ch & 1;
        stsA(buf);
        asm volatile("cp.async.wait_group 0;" ::: "memory");
        __syncthreads();
        if (ch + 1 < NCH) {
            ldgA(ch + 1);
            cpB(ch + 1, buf ^ 1);
            asm volatile("cp.async.commit_group;" ::: "memory");
        }

        const uint32_t aA0 = sA[buf] + aOff[0];
        const uint32_t aA1 = sA[buf] + aOff[1];
        const uint32_t bA0 = sB[buf] + bOff[0];
        const uint32_t bA1 = sB[buf] + bOff[1];
        const uint32_t bA2 = sB[buf] + bOff[2];
        const uint32_t bA3 = sB[buf] + bOff[3];

#pragma unroll
        for (int ks = 0; ks < 4; ks++) {
            const uint32_t x = (uint32_t)(ks << 5);   // XOR address step
            uint32_t a[2][4], b[4][4];
            ldsm_x4(a[0], aA0 ^ x);
            ldsm_x4(a[1], aA1 ^ x);
            ldsm_x4(b[0], bA0 ^ x);
            ldsm_x4(b[1], bA1 ^ x);
            ldsm_x4(b[2], bA2 ^ x);
            ldsm_x4(b[3], bA3 ^ x);
#pragma unroll
            for (int p = 0; p < 4; p++) {
#pragma unroll
                for (int s = 0; s < 2; s++) {
                    const int nt = 2 * p + s;
#pragma unroll
                    for (int mt = 0; mt < 2; mt++) {
                        asm volatile(
                            "mma.sync.aligned.m16n8k16.row.col.f32.f16.f16.f32 "
                            "{%0,%1,%2,%3}, {%4,%5,%6,%7}, {%8,%9}, {%0,%1,%2,%3};\n"
                            : "+f"(acc[mt][nt][0]), "+f"(acc[mt][nt][1]),
                              "+f"(acc[mt][nt][2]), "+f"(acc[mt][nt][3])
                            : "r"(a[mt][0]), "r"(a[mt][1]), "r"(a[mt][2]), "r"(a[mt][3]),
                              "r"(b[p][2*s]), "r"(b[p][2*s+1]));
                    }
                }
            }
        }
    }

    // ---- epilogue: bias + relu, float2 stores ----
    const int xr = lane >> 2;
#pragma unroll
    for (int mt = 0; mt < 2; mt++) {
        const int m0 = ctaM + warpM * 32 + mt * 16 + xr;
#pragma unroll
        for (int nt = 0; nt < 8; nt++) {
            const int n0 = warpN * 64 + nt * 8 + 2 * (lane & 3);
            const float bv0 = __ldg(&bias[n0]);
            const float bv1 = __ldg(&bias[n0 + 1]);
            float v0 = fmaxf(acc[mt][nt][0] + bv0, 0.0f);
            float v1 = fmaxf(acc[mt][nt][1] + bv1, 0.0f);
            float v2 = fmaxf(acc[mt][nt][2] + bv0, 0.0f);
            float v3 = fmaxf(acc[mt][nt][3] + bv1, 0.0f);
            *(float2*)&Out[(size_t)m0 * NDIM + n0]       = make_float2(v0, v1);
            *(float2*)&Out[(size_t)(m0 + 8) * NDIM + n0] = make_float2(v2, v3);
        }
    }
}

extern "C" void kernel_launch(void* const* d_in, const int* in_sizes, int n_in,
                              void* d_out, int out_size)
{
    const float* x = (const float*)d_in[0];   // [131072, 256]
    const float* W = (const float*)d_in[1];   // [256, 256]
    const float* b = (const float*)d_in[2];   // [256]
    float* out = (float*)d_out;

    convW_kernel<<<64, 1024>>>(W);

    cudaFuncSetAttribute(gemm_f16_ldsm,
                         cudaFuncAttributeMaxDynamicSharedMemorySize, SMEM_BYTES);
    dim3 grid(131072 / BM);                   // 1024 CTAs, full N per CTA
    gemm_f16_ldsm<<<grid, 512, SMEM_BYTES>>>(x, b, out);
}